// round 1
// baseline (speedup 1.0000x reference)
#include <cuda_runtime.h>
#include <math.h>

#define B_    4
#define S_    2048
#define D_    768
#define H_    12
#define HD    64
#define QKV_N (3*D_)      // 2304
#define M_    (B_*S_)     // 8192

// Scratch (no cudaMalloc allowed): ~75.5MB + ~25MB
__device__ float g_qkv[M_ * QKV_N];
__device__ float g_att[M_ * D_];

// ---------------------------------------------------------------------------
// Tiled fp32 GEMM: C[M,N] = A[M,K] @ B[K,N] + bias[N]
// BM=BN=128, BK=16, 256 threads, 8x8 per thread.
// ---------------------------------------------------------------------------
__global__ __launch_bounds__(256)
void gemm_bias_kernel(const float* __restrict__ A,
                      const float* __restrict__ Bm,
                      const float* __restrict__ bias,
                      float* __restrict__ C,
                      int M, int N, int K)
{
    const int BM = 128, BN = 128, BK = 16;
    __shared__ float As[BK][BM];   // A tile stored transposed
    __shared__ float Bs[BK][BN];

    int tid = threadIdx.x;
    int tx = tid & 15;        // 0..15 -> N direction
    int ty = tid >> 4;        // 0..15 -> M direction
    int m0 = blockIdx.y * BM;
    int n0 = blockIdx.x * BN;

    float acc[8][8];
#pragma unroll
    for (int i = 0; i < 8; ++i)
#pragma unroll
        for (int j = 0; j < 8; ++j) acc[i][j] = 0.f;

    for (int k0 = 0; k0 < K; k0 += BK) {
        // Load A tile 128x16, store transposed into As[k][m]
#pragma unroll
        for (int it = 0; it < 2; ++it) {
            int f4 = tid + it * 256;            // 512 float4 total
            int r  = f4 >> 2;                   // 4 float4 per row of 16
            int c  = (f4 & 3) * 4;
            float4 v = *(const float4*)&A[(long)(m0 + r) * K + k0 + c];
            As[c + 0][r] = v.x;
            As[c + 1][r] = v.y;
            As[c + 2][r] = v.z;
            As[c + 3][r] = v.w;
        }
        // Load B tile 16x128 directly
#pragma unroll
        for (int it = 0; it < 2; ++it) {
            int f4 = tid + it * 256;
            int r  = f4 >> 5;                   // 32 float4 per row of 128
            int c  = (f4 & 31) * 4;
            *(float4*)&Bs[r][c] = *(const float4*)&Bm[(long)(k0 + r) * N + n0 + c];
        }
        __syncthreads();

#pragma unroll
        for (int kk = 0; kk < BK; ++kk) {
            float a[8], b[8];
            *(float4*)&a[0] = *(float4*)&As[kk][ty * 8];
            *(float4*)&a[4] = *(float4*)&As[kk][ty * 8 + 4];
            *(float4*)&b[0] = *(float4*)&Bs[kk][tx * 8];
            *(float4*)&b[4] = *(float4*)&Bs[kk][tx * 8 + 4];
#pragma unroll
            for (int i = 0; i < 8; ++i)
#pragma unroll
                for (int j = 0; j < 8; ++j)
                    acc[i][j] = fmaf(a[i], b[j], acc[i][j]);
        }
        __syncthreads();
    }

    // Epilogue: + bias
    float bv[8];
#pragma unroll
    for (int j = 0; j < 8; ++j) bv[j] = bias[n0 + tx * 8 + j];

#pragma unroll
    for (int i = 0; i < 8; ++i) {
        long row = m0 + ty * 8 + i;
        float4 o0, o1;
        o0.x = acc[i][0] + bv[0];
        o0.y = acc[i][1] + bv[1];
        o0.z = acc[i][2] + bv[2];
        o0.w = acc[i][3] + bv[3];
        o1.x = acc[i][4] + bv[4];
        o1.y = acc[i][5] + bv[5];
        o1.z = acc[i][6] + bv[6];
        o1.w = acc[i][7] + bv[7];
        *(float4*)&C[row * N + n0 + tx * 8]     = o0;
        *(float4*)&C[row * N + n0 + tx * 8 + 4] = o1;
    }
}

// ---------------------------------------------------------------------------
// Flash attention (fp32, causal). One block = 64 query rows of one (b,h).
// Iterates K/V tiles of 64 rows; online softmax; causal tiles skipped.
// ---------------------------------------------------------------------------
__global__ __launch_bounds__(256)
void flash_attn_kernel(const float* __restrict__ qkv, float* __restrict__ att)
{
    extern __shared__ float sm[];
    float* Qs = sm;                 // [64][65]
    float* Ks = Qs + 64 * 65;       // [64][65]
    float* Vs = Ks + 64 * 65;       // [64][65]
    float* Ps = Vs + 64 * 65;       // [64][65]

    int tid = threadIdx.x;
    int tx  = tid & 15;             // k-col / hd-col group
    int ty  = tid >> 4;             // q-row group
    int qt  = blockIdx.x;
    int bh  = blockIdx.y;
    int b   = bh / H_;
    int h   = bh - b * H_;
    int q0  = qt * 64;
    const long rowbase = (long)b * S_ * QKV_N;

    // Load Q tile, pre-scaled by 1/sqrt(hd)=0.125
#pragma unroll
    for (int it = 0; it < 4; ++it) {
        int f = (tid + it * 256) * 4;       // 0..4095
        int r = f >> 6, c = f & 63;
        float4 v = *(const float4*)&qkv[rowbase + (long)(q0 + r) * QKV_N + h * HD + c];
        Qs[r * 65 + c]     = v.x * 0.125f;
        Qs[r * 65 + c + 1] = v.y * 0.125f;
        Qs[r * 65 + c + 2] = v.z * 0.125f;
        Qs[r * 65 + c + 3] = v.w * 0.125f;
    }

    float acc[4][4];
    float mrow[4], lrow[4];
#pragma unroll
    for (int i = 0; i < 4; ++i) {
        mrow[i] = -INFINITY;
        lrow[i] = 0.f;
#pragma unroll
        for (int j = 0; j < 4; ++j) acc[i][j] = 0.f;
    }

    for (int kt = 0; kt <= qt; ++kt) {
        int k0 = kt * 64;
        // Load K and V tiles
#pragma unroll
        for (int it = 0; it < 4; ++it) {
            int f = (tid + it * 256) * 4;
            int r = f >> 6, c = f & 63;
            long base = rowbase + (long)(k0 + r) * QKV_N + h * HD + c;
            float4 kv = *(const float4*)&qkv[base + D_];
            Ks[r * 65 + c]     = kv.x;
            Ks[r * 65 + c + 1] = kv.y;
            Ks[r * 65 + c + 2] = kv.z;
            Ks[r * 65 + c + 3] = kv.w;
            float4 vv = *(const float4*)&qkv[base + 2 * D_];
            Vs[r * 65 + c]     = vv.x;
            Vs[r * 65 + c + 1] = vv.y;
            Vs[r * 65 + c + 2] = vv.z;
            Vs[r * 65 + c + 3] = vv.w;
        }
        __syncthreads();

        // S = Q K^T (4x4 per thread)
        float sc[4][4];
#pragma unroll
        for (int i = 0; i < 4; ++i)
#pragma unroll
            for (int j = 0; j < 4; ++j) sc[i][j] = 0.f;

#pragma unroll 16
        for (int kk = 0; kk < 64; ++kk) {
            float qf[4], kf[4];
#pragma unroll
            for (int i = 0; i < 4; ++i) qf[i] = Qs[(ty * 4 + i) * 65 + kk];
#pragma unroll
            for (int j = 0; j < 4; ++j) kf[j] = Ks[(tx * 4 + j) * 65 + kk];
#pragma unroll
            for (int i = 0; i < 4; ++i)
#pragma unroll
                for (int j = 0; j < 4; ++j)
                    sc[i][j] = fmaf(qf[i], kf[j], sc[i][j]);
        }

        if (kt == qt) {
#pragma unroll
            for (int i = 0; i < 4; ++i)
#pragma unroll
                for (int j = 0; j < 4; ++j)
                    if (tx * 4 + j > ty * 4 + i) sc[i][j] = -INFINITY;
        }

        // Online softmax per query row (row group = 16 lanes sharing ty)
#pragma unroll
        for (int i = 0; i < 4; ++i) {
            float rm = sc[i][0];
#pragma unroll
            for (int j = 1; j < 4; ++j) rm = fmaxf(rm, sc[i][j]);
#pragma unroll
            for (int m = 8; m >= 1; m >>= 1)
                rm = fmaxf(rm, __shfl_xor_sync(0xffffffffu, rm, m));
            float mn    = fmaxf(mrow[i], rm);
            float alpha = __expf(mrow[i] - mn);
            mrow[i] = mn;
            float rs = 0.f;
#pragma unroll
            for (int j = 0; j < 4; ++j) {
                float p = __expf(sc[i][j] - mn);
                sc[i][j] = p;
                rs += p;
            }
#pragma unroll
            for (int m = 8; m >= 1; m >>= 1)
                rs += __shfl_xor_sync(0xffffffffu, rs, m);
            lrow[i] = lrow[i] * alpha + rs;
#pragma unroll
            for (int j = 0; j < 4; ++j) acc[i][j] *= alpha;
#pragma unroll
            for (int j = 0; j < 4; ++j)
                Ps[(ty * 4 + i) * 65 + tx * 4 + j] = sc[i][j];
        }
        __syncthreads();

        // O += P @ V  (thread now owns 4 q-rows x 4 hd-cols)
#pragma unroll 16
        for (int kk = 0; kk < 64; ++kk) {
            float pf[4], vf[4];
#pragma unroll
            for (int i = 0; i < 4; ++i) pf[i] = Ps[(ty * 4 + i) * 65 + kk];
#pragma unroll
            for (int j = 0; j < 4; ++j) vf[j] = Vs[kk * 65 + tx * 4 + j];
#pragma unroll
            for (int i = 0; i < 4; ++i)
#pragma unroll
                for (int j = 0; j < 4; ++j)
                    acc[i][j] = fmaf(pf[i], vf[j], acc[i][j]);
        }
        __syncthreads();
    }

    // Normalize and store into [B,S,D] layout (merge heads)
#pragma unroll
    for (int i = 0; i < 4; ++i) {
        float inv = 1.f / lrow[i];
        long  q   = q0 + ty * 4 + i;
        float4 o;
        o.x = acc[i][0] * inv;
        o.y = acc[i][1] * inv;
        o.z = acc[i][2] * inv;
        o.w = acc[i][3] * inv;
        *(float4*)&att[((long)b * S_ + q) * D_ + h * HD + tx * 4] = o;
    }
}

// ---------------------------------------------------------------------------
extern "C" void kernel_launch(void* const* d_in, const int* in_sizes, int n_in,
                              void* d_out, int out_size)
{
    const float* x    = (const float*)d_in[0];
    const float* Wqkv = (const float*)d_in[1];
    const float* bqkv = (const float*)d_in[2];
    const float* Wp   = (const float*)d_in[3];
    const float* bp   = (const float*)d_in[4];
    float* out = (float*)d_out;

    float *qkv, *att;
    cudaGetSymbolAddress((void**)&qkv, g_qkv);
    cudaGetSymbolAddress((void**)&att, g_att);

    // 1) QKV projection: [8192,768] @ [768,2304] + bias
    gemm_bias_kernel<<<dim3(QKV_N / 128, M_ / 128), 256>>>(
        x, Wqkv, bqkv, qkv, M_, QKV_N, D_);

    // 2) causal flash attention
    size_t smem = 4 * 64 * 65 * sizeof(float);   // 66,560 B
    cudaFuncSetAttribute(flash_attn_kernel,
                         cudaFuncAttributeMaxDynamicSharedMemorySize, (int)smem);
    flash_attn_kernel<<<dim3(S_ / 64, B_ * H_), 256, smem>>>(qkv, att);

    // 3) output projection: [8192,768] @ [768,768] + bias
    gemm_bias_kernel<<<dim3(D_ / 128, M_ / 128), 256>>>(
        att, Wp, bp, out, M_, D_, D_);
}

// round 4
// speedup vs baseline: 1.2679x; 1.2679x over previous
#include <cuda_runtime.h>
#include <cuda_bf16.h>
#include <cstdint>
#include <math.h>

#define B_    4
#define S_    2048
#define D_    768
#define H_    12
#define HD    64
#define QKV_N (3*D_)      // 2304
#define M_    (B_*S_)     // 8192

// Scratch (no cudaMalloc allowed)
__device__ float g_qkv[M_ * QKV_N];
__device__ float g_att[M_ * D_];
__device__ __nv_bfloat16 g_ah[M_ * D_];
__device__ __nv_bfloat16 g_al[M_ * D_];
__device__ __nv_bfloat16 g_bh[QKV_N * D_];
__device__ __nv_bfloat16 g_bl[QKV_N * D_];

// ---------------------------------------------------------------------------
__device__ __forceinline__ uint32_t smem_u32(const void* p) {
    uint32_t a;
    asm("{ .reg .u64 t; cvta.to.shared.u64 t, %1; cvt.u32.u64 %0, t; }" : "=r"(a) : "l"(p));
    return a;
}

#define LDM_X4(r, addr) \
    asm volatile("ldmatrix.sync.aligned.m8n8.x4.shared.b16 {%0,%1,%2,%3}, [%4];" \
        : "=r"((r)[0]), "=r"((r)[1]), "=r"((r)[2]), "=r"((r)[3]) : "r"(addr))
#define LDM_X2(r, addr) \
    asm volatile("ldmatrix.sync.aligned.m8n8.x2.shared.b16 {%0,%1}, [%2];" \
        : "=r"((r)[0]), "=r"((r)[1]) : "r"(addr))
#define MMA_BF16(d, a, b) \
    asm volatile("mma.sync.aligned.m16n8k16.row.col.f32.bf16.bf16.f32 " \
        "{%0,%1,%2,%3}, {%4,%5,%6,%7}, {%8,%9}, {%0,%1,%2,%3};" \
        : "+f"((d)[0]), "+f"((d)[1]), "+f"((d)[2]), "+f"((d)[3]) \
        : "r"((a)[0]), "r"((a)[1]), "r"((a)[2]), "r"((a)[3]), \
          "r"((b)[0]), "r"((b)[1]))

// ---------------------------------------------------------------------------
// fp32 -> bf16 hi/lo split (elementwise)
// ---------------------------------------------------------------------------
__global__ void split_kernel(const float* __restrict__ in,
                             __nv_bfloat16* __restrict__ hi,
                             __nv_bfloat16* __restrict__ lo, int n4)
{
    int i = blockIdx.x * blockDim.x + threadIdx.x;
    if (i >= n4) return;
    float4 v = ((const float4*)in)[i];
    __nv_bfloat16 h0 = __float2bfloat16(v.x), h1 = __float2bfloat16(v.y);
    __nv_bfloat16 h2 = __float2bfloat16(v.z), h3 = __float2bfloat16(v.w);
    __nv_bfloat16 l0 = __float2bfloat16(v.x - __bfloat162float(h0));
    __nv_bfloat16 l1 = __float2bfloat16(v.y - __bfloat162float(h1));
    __nv_bfloat16 l2 = __float2bfloat16(v.z - __bfloat162float(h2));
    __nv_bfloat16 l3 = __float2bfloat16(v.w - __bfloat162float(h3));
    ((__nv_bfloat162*)hi)[2*i]   = __nv_bfloat162(h0, h1);
    ((__nv_bfloat162*)hi)[2*i+1] = __nv_bfloat162(h2, h3);
    ((__nv_bfloat162*)lo)[2*i]   = __nv_bfloat162(l0, l1);
    ((__nv_bfloat162*)lo)[2*i+1] = __nv_bfloat162(l2, l3);
}

// W[K,N] fp32 -> Bh/Bl[N,K] bf16 (transpose + split)
__global__ void transpose_split_kernel(const float* __restrict__ W,
                                       __nv_bfloat16* __restrict__ Bh,
                                       __nv_bfloat16* __restrict__ Bl,
                                       int K, int N)
{
    __shared__ float t[32][33];
    int n0 = blockIdx.x * 32, k0 = blockIdx.y * 32;
    int tx = threadIdx.x, ty = threadIdx.y;
#pragma unroll
    for (int j = 0; j < 4; ++j)
        t[ty + j*8][tx] = W[(long)(k0 + ty + j*8) * N + n0 + tx];
    __syncthreads();
#pragma unroll
    for (int j = 0; j < 4; ++j) {
        float v = t[tx][ty + j*8];
        __nv_bfloat16 h = __float2bfloat16(v);
        __nv_bfloat16 l = __float2bfloat16(v - __bfloat162float(h));
        long o = (long)(n0 + ty + j*8) * K + k0 + tx;
        Bh[o] = h;
        Bl[o] = l;
    }
}

// ---------------------------------------------------------------------------
// bf16x3 GEMM via mma.sync: C[M,N] = A[M,K] @ Bt[N,K]^T + bias (fp32-accurate)
// Block tile 128x128, BK=32, 8 warps (2x4), warp tile 64x32.
// ---------------------------------------------------------------------------
#define LDA 40   // padded row length in bf16 (80B) -> conflict-free ldmatrix

__global__ __launch_bounds__(256)
void gemm_mma_kernel(const __nv_bfloat16* __restrict__ Ah,
                     const __nv_bfloat16* __restrict__ Al,
                     const __nv_bfloat16* __restrict__ Bh,
                     const __nv_bfloat16* __restrict__ Bl,
                     const float* __restrict__ bias,
                     float* __restrict__ C,
                     int M, int N, int K)
{
    __shared__ __nv_bfloat16 sAh[128 * LDA];
    __shared__ __nv_bfloat16 sAl[128 * LDA];
    __shared__ __nv_bfloat16 sBh[128 * LDA];
    __shared__ __nv_bfloat16 sBl[128 * LDA];

    const int tid  = threadIdx.x;
    const int lane = tid & 31;
    const int wid  = tid >> 5;
    const int wm   = wid >> 2;           // 0..1
    const int wn   = wid & 3;            // 0..3
    const int m0   = blockIdx.y * 128;
    const int n0   = blockIdx.x * 128;

    const uint32_t uAh = smem_u32(sAh);
    const uint32_t uAl = smem_u32(sAl);
    const uint32_t uBh = smem_u32(sBh);
    const uint32_t uBl = smem_u32(sBl);

    float acc[4][4][4];
#pragma unroll
    for (int i = 0; i < 4; ++i)
#pragma unroll
        for (int j = 0; j < 4; ++j)
#pragma unroll
            for (int r = 0; r < 4; ++r) acc[i][j][r] = 0.f;

    // precomputed ldmatrix lane addressing
    const int a_row = lane & 15;               // row within 16-row tile
    const int a_kb  = (lane >> 4) * 8;         // k sub-block 0/8
    const int b_row = lane & 7;
    const int b_kb  = ((lane >> 3) & 1) * 8;

    for (int k0 = 0; k0 < K; k0 += 32) {
        __syncthreads();
        // load 4 tiles of [128 x 32] bf16
#pragma unroll
        for (int it = 0; it < 2; ++it) {
            int chunk = tid + it * 256;        // 0..511
            int r = chunk >> 2;
            int c = chunk & 3;                 // 8-bf16 groups
            long gA = (long)(m0 + r) * K + k0 + c * 8;
            long gB = (long)(n0 + r) * K + k0 + c * 8;
            int so = r * LDA + c * 8;
            *(uint4*)&sAh[so] = *(const uint4*)&Ah[gA];
            *(uint4*)&sAl[so] = *(const uint4*)&Al[gA];
            *(uint4*)&sBh[so] = *(const uint4*)&Bh[gB];
            *(uint4*)&sBl[so] = *(const uint4*)&Bl[gB];
        }
        __syncthreads();

#pragma unroll
        for (int ks = 0; ks < 2; ++ks) {
            const int kc = ks * 16;
            // B fragments for all 4 n-tiles
            uint32_t bh[4][2], bl[4][2];
#pragma unroll
            for (int j = 0; j < 4; ++j) {
                uint32_t off = ((wn * 32 + j * 8 + b_row) * LDA + kc + b_kb) * 2;
                LDM_X2(bh[j], uBh + off);
                LDM_X2(bl[j], uBl + off);
            }
#pragma unroll
            for (int i = 0; i < 4; ++i) {
                uint32_t off = ((wm * 64 + i * 16 + a_row) * LDA + kc + a_kb) * 2;
                uint32_t ah[4], al[4];
                LDM_X4(ah, uAh + off);
                LDM_X4(al, uAl + off);
#pragma unroll
                for (int j = 0; j < 4; ++j) {
                    MMA_BF16(acc[i][j], ah, bh[j]);
                    MMA_BF16(acc[i][j], ah, bl[j]);
                    MMA_BF16(acc[i][j], al, bh[j]);
                }
            }
        }
    }

    // epilogue: direct float2 stores + bias
    const int qr = lane >> 2;          // 0..7
    const int qc = (lane & 3) * 2;     // 0,2,4,6
#pragma unroll
    for (int i = 0; i < 4; ++i) {
#pragma unroll
        for (int j = 0; j < 4; ++j) {
            int col = n0 + wn * 32 + j * 8 + qc;
            float b0 = __ldg(&bias[col]);
            float b1 = __ldg(&bias[col + 1]);
            long r0 = m0 + wm * 64 + i * 16 + qr;
            float2 v0 = make_float2(acc[i][j][0] + b0, acc[i][j][1] + b1);
            float2 v1 = make_float2(acc[i][j][2] + b0, acc[i][j][3] + b1);
            *(float2*)&C[r0 * N + col]       = v0;
            *(float2*)&C[(r0 + 8) * N + col] = v1;
        }
    }
}

// ---------------------------------------------------------------------------
// Flash attention (fp32, causal). One block = 64 query rows of one (b,h).
// ---------------------------------------------------------------------------
__global__ __launch_bounds__(256)
void flash_attn_kernel(const float* __restrict__ qkv, float* __restrict__ att)
{
    extern __shared__ float sm[];
    float* Qs = sm;                 // [64][65]
    float* Ks = Qs + 64 * 65;
    float* Vs = Ks + 64 * 65;
    float* Ps = Vs + 64 * 65;

    int tid = threadIdx.x;
    int tx  = tid & 15;
    int ty  = tid >> 4;
    int qt  = blockIdx.x;
    int bh  = blockIdx.y;
    int b   = bh / H_;
    int h   = bh - b * H_;
    int q0  = qt * 64;
    const long rowbase = (long)b * S_ * QKV_N;

#pragma unroll
    for (int it = 0; it < 4; ++it) {
        int f = (tid + it * 256) * 4;
        int r = f >> 6, c = f & 63;
        float4 v = *(const float4*)&qkv[rowbase + (long)(q0 + r) * QKV_N + h * HD + c];
        Qs[r * 65 + c]     = v.x * 0.125f;
        Qs[r * 65 + c + 1] = v.y * 0.125f;
        Qs[r * 65 + c + 2] = v.z * 0.125f;
        Qs[r * 65 + c + 3] = v.w * 0.125f;
    }

    float acc[4][4];
    float mrow[4], lrow[4];
#pragma unroll
    for (int i = 0; i < 4; ++i) {
        mrow[i] = -INFINITY;
        lrow[i] = 0.f;
#pragma unroll
        for (int j = 0; j < 4; ++j) acc[i][j] = 0.f;
    }

    for (int kt = 0; kt <= qt; ++kt) {
        int k0 = kt * 64;
#pragma unroll
        for (int it = 0; it < 4; ++it) {
            int f = (tid + it * 256) * 4;
            int r = f >> 6, c = f & 63;
            long base = rowbase + (long)(k0 + r) * QKV_N + h * HD + c;
            float4 kv = *(const float4*)&qkv[base + D_];
            Ks[r * 65 + c]     = kv.x;
            Ks[r * 65 + c + 1] = kv.y;
            Ks[r * 65 + c + 2] = kv.z;
            Ks[r * 65 + c + 3] = kv.w;
            float4 vv = *(const float4*)&qkv[base + 2 * D_];
            Vs[r * 65 + c]     = vv.x;
            Vs[r * 65 + c + 1] = vv.y;
            Vs[r * 65 + c + 2] = vv.z;
            Vs[r * 65 + c + 3] = vv.w;
        }
        __syncthreads();

        float sc[4][4];
#pragma unroll
        for (int i = 0; i < 4; ++i)
#pragma unroll
            for (int j = 0; j < 4; ++j) sc[i][j] = 0.f;

#pragma unroll 16
        for (int kk = 0; kk < 64; ++kk) {
            float qf[4], kf[4];
#pragma unroll
            for (int i = 0; i < 4; ++i) qf[i] = Qs[(ty * 4 + i) * 65 + kk];
#pragma unroll
            for (int j = 0; j < 4; ++j) kf[j] = Ks[(tx * 4 + j) * 65 + kk];
#pragma unroll
            for (int i = 0; i < 4; ++i)
#pragma unroll
                for (int j = 0; j < 4; ++j)
                    sc[i][j] = fmaf(qf[i], kf[j], sc[i][j]);
        }

        if (kt == qt) {
#pragma unroll
            for (int i = 0; i < 4; ++i)
#pragma unroll
                for (int j = 0; j < 4; ++j)
                    if (tx * 4 + j > ty * 4 + i) sc[i][j] = -INFINITY;
        }

#pragma unroll
        for (int i = 0; i < 4; ++i) {
            float rm = sc[i][0];
#pragma unroll
            for (int j = 1; j < 4; ++j) rm = fmaxf(rm, sc[i][j]);
#pragma unroll
            for (int m = 8; m >= 1; m >>= 1)
                rm = fmaxf(rm, __shfl_xor_sync(0xffffffffu, rm, m));
            float mn    = fmaxf(mrow[i], rm);
            float alpha = __expf(mrow[i] - mn);
            mrow[i] = mn;
            float rs = 0.f;
#pragma unroll
            for (int j = 0; j < 4; ++j) {
                float p = __expf(sc[i][j] - mn);
                sc[i][j] = p;
                rs += p;
            }
#pragma unroll
            for (int m = 8; m >= 1; m >>= 1)
                rs += __shfl_xor_sync(0xffffffffu, rs, m);
            lrow[i] = lrow[i] * alpha + rs;
#pragma unroll
            for (int j = 0; j < 4; ++j) acc[i][j] *= alpha;
#pragma unroll
            for (int j = 0; j < 4; ++j)
                Ps[(ty * 4 + i) * 65 + tx * 4 + j] = sc[i][j];
        }
        __syncthreads();

#pragma unroll 16
        for (int kk = 0; kk < 64; ++kk) {
            float pf[4], vf[4];
#pragma unroll
            for (int i = 0; i < 4; ++i) pf[i] = Ps[(ty * 4 + i) * 65 + kk];
#pragma unroll
            for (int j = 0; j < 4; ++j) vf[j] = Vs[kk * 65 + tx * 4 + j];
#pragma unroll
            for (int i = 0; i < 4; ++i)
#pragma unroll
                for (int j = 0; j < 4; ++j)
                    acc[i][j] = fmaf(pf[i], vf[j], acc[i][j]);
        }
        __syncthreads();
    }

#pragma unroll
    for (int i = 0; i < 4; ++i) {
        float inv = 1.f / lrow[i];
        long  q   = q0 + ty * 4 + i;
        float4 o;
        o.x = acc[i][0] * inv;
        o.y = acc[i][1] * inv;
        o.z = acc[i][2] * inv;
        o.w = acc[i][3] * inv;
        *(float4*)&att[((long)b * S_ + q) * D_ + h * HD + tx * 4] = o;
    }
}

// ---------------------------------------------------------------------------
extern "C" void kernel_launch(void* const* d_in, const int* in_sizes, int n_in,
                              void* d_out, int out_size)
{
    const float* x    = (const float*)d_in[0];
    const float* Wqkv = (const float*)d_in[1];
    const float* bqkv = (const float*)d_in[2];
    const float* Wp   = (const float*)d_in[3];
    const float* bp   = (const float*)d_in[4];
    float* out = (float*)d_out;

    float *qkv, *att;
    __nv_bfloat16 *ah, *al, *bh, *bl;
    cudaGetSymbolAddress((void**)&qkv, g_qkv);
    cudaGetSymbolAddress((void**)&att, g_att);
    cudaGetSymbolAddress((void**)&ah, g_ah);
    cudaGetSymbolAddress((void**)&al, g_al);
    cudaGetSymbolAddress((void**)&bh, g_bh);
    cudaGetSymbolAddress((void**)&bl, g_bl);

    const int n4 = M_ * D_ / 4;

    // 1) split x, transpose+split Wqkv, tensor-core QKV GEMM
    split_kernel<<<(n4 + 255) / 256, 256>>>(x, ah, al, n4);
    transpose_split_kernel<<<dim3(QKV_N / 32, D_ / 32), dim3(32, 8)>>>(Wqkv, bh, bl, D_, QKV_N);
    gemm_mma_kernel<<<dim3(QKV_N / 128, M_ / 128), 256>>>(
        ah, al, bh, bl, bqkv, qkv, M_, QKV_N, D_);

    // 2) causal flash attention (fp32)
    size_t smem = 4 * 64 * 65 * sizeof(float);
    cudaFuncSetAttribute(flash_attn_kernel,
                         cudaFuncAttributeMaxDynamicSharedMemorySize, (int)smem);
    flash_attn_kernel<<<dim3(S_ / 64, B_ * H_), 256, smem>>>(qkv, att);

    // 3) split att, transpose+split Wp, tensor-core proj GEMM
    split_kernel<<<(n4 + 255) / 256, 256>>>(att, ah, al, n4);
    transpose_split_kernel<<<dim3(D_ / 32, D_ / 32), dim3(32, 8)>>>(Wp, bh, bl, D_, D_);
    gemm_mma_kernel<<<dim3(D_ / 128, M_ / 128), 256>>>(
        ah, al, bh, bl, bp, out, M_, D_, D_);
}

// round 7
// speedup vs baseline: 2.1843x; 1.7228x over previous
#include <cuda_runtime.h>
#include <cuda_bf16.h>
#include <cstdint>
#include <math.h>

#define B_    4
#define S_    2048
#define D_    768
#define H_    12
#define HD    64
#define QKV_N (3*D_)      // 2304
#define M_    (B_*S_)     // 8192

// Scratch (no cudaMalloc allowed)
__device__ float g_qkv[M_ * QKV_N];
__device__ __nv_bfloat16 g_ah[M_ * D_];
__device__ __nv_bfloat16 g_al[M_ * D_];
__device__ __nv_bfloat16 g_bh[QKV_N * D_];
__device__ __nv_bfloat16 g_bl[QKV_N * D_];

// ---------------------------------------------------------------------------
__device__ __forceinline__ uint32_t smem_u32(const void* p) {
    uint32_t a;
    asm("{ .reg .u64 t; cvta.to.shared.u64 t, %1; cvt.u32.u64 %0, t; }" : "=r"(a) : "l"(p));
    return a;
}

#define LDM_X4(r, addr) \
    asm volatile("ldmatrix.sync.aligned.m8n8.x4.shared.b16 {%0,%1,%2,%3}, [%4];" \
        : "=r"((r)[0]), "=r"((r)[1]), "=r"((r)[2]), "=r"((r)[3]) : "r"(addr))
#define LDM_X4T(r, addr) \
    asm volatile("ldmatrix.sync.aligned.m8n8.x4.trans.shared.b16 {%0,%1,%2,%3}, [%4];" \
        : "=r"((r)[0]), "=r"((r)[1]), "=r"((r)[2]), "=r"((r)[3]) : "r"(addr))
#define LDM_X2(r, addr) \
    asm volatile("ldmatrix.sync.aligned.m8n8.x2.shared.b16 {%0,%1}, [%2];" \
        : "=r"((r)[0]), "=r"((r)[1]) : "r"(addr))
#define MMA_BF16(d, a, b) \
    asm volatile("mma.sync.aligned.m16n8k16.row.col.f32.bf16.bf16.f32 " \
        "{%0,%1,%2,%3}, {%4,%5,%6,%7}, {%8,%9}, {%0,%1,%2,%3};" \
        : "+f"((d)[0]), "+f"((d)[1]), "+f"((d)[2]), "+f"((d)[3]) \
        : "r"((a)[0]), "r"((a)[1]), "r"((a)[2]), "r"((a)[3]), \
          "r"((b)[0]), "r"((b)[1]))
#define MMA_BF16R(d, a, b0r, b1r) \
    asm volatile("mma.sync.aligned.m16n8k16.row.col.f32.bf16.bf16.f32 " \
        "{%0,%1,%2,%3}, {%4,%5,%6,%7}, {%8,%9}, {%0,%1,%2,%3};" \
        : "+f"((d)[0]), "+f"((d)[1]), "+f"((d)[2]), "+f"((d)[3]) \
        : "r"((a)[0]), "r"((a)[1]), "r"((a)[2]), "r"((a)[3]), \
          "r"(b0r), "r"(b1r))

__device__ __forceinline__ uint32_t pack_bf2(float lo, float hi) {
    uint32_t r;
    asm("cvt.rn.bf16x2.f32 %0, %1, %2;" : "=r"(r) : "f"(hi), "f"(lo));
    return r;
}

// store 4 consecutive fp32 values as hi/lo bf16 pairs
__device__ __forceinline__ void store_split4(__nv_bfloat16* ph, __nv_bfloat16* pl, float4 v) {
    __nv_bfloat16 h0 = __float2bfloat16(v.x), h1 = __float2bfloat16(v.y);
    __nv_bfloat16 h2 = __float2bfloat16(v.z), h3 = __float2bfloat16(v.w);
    *(__nv_bfloat162*)(ph)     = __nv_bfloat162(h0, h1);
    *(__nv_bfloat162*)(ph + 2) = __nv_bfloat162(h2, h3);
    *(__nv_bfloat162*)(pl)     = __nv_bfloat162(
        __float2bfloat16(v.x - __bfloat162float(h0)),
        __float2bfloat16(v.y - __bfloat162float(h1)));
    *(__nv_bfloat162*)(pl + 2) = __nv_bfloat162(
        __float2bfloat16(v.z - __bfloat162float(h2)),
        __float2bfloat16(v.w - __bfloat162float(h3)));
}

// ---------------------------------------------------------------------------
// fp32 -> bf16 hi/lo split (elementwise)
// ---------------------------------------------------------------------------
__global__ void split_kernel(const float* __restrict__ in,
                             __nv_bfloat16* __restrict__ hi,
                             __nv_bfloat16* __restrict__ lo, int n4)
{
    int i = blockIdx.x * blockDim.x + threadIdx.x;
    if (i >= n4) return;
    float4 v = ((const float4*)in)[i];
    store_split4(hi + 4 * (long)i, lo + 4 * (long)i, v);
}

// W[K,N] fp32 -> Bh/Bl[N,K] bf16 (transpose + split)
__global__ void transpose_split_kernel(const float* __restrict__ W,
                                       __nv_bfloat16* __restrict__ Bh,
                                       __nv_bfloat16* __restrict__ Bl,
                                       int K, int N)
{
    __shared__ float t[32][33];
    int n0 = blockIdx.x * 32, k0 = blockIdx.y * 32;
    int tx = threadIdx.x, ty = threadIdx.y;
#pragma unroll
    for (int j = 0; j < 4; ++j)
        t[ty + j*8][tx] = W[(long)(k0 + ty + j*8) * N + n0 + tx];
    __syncthreads();
#pragma unroll
    for (int j = 0; j < 4; ++j) {
        float v = t[tx][ty + j*8];
        __nv_bfloat16 h = __float2bfloat16(v);
        __nv_bfloat16 l = __float2bfloat16(v - __bfloat162float(h));
        long o = (long)(n0 + ty + j*8) * K + k0 + tx;
        Bh[o] = h;
        Bl[o] = l;
    }
}

// ---------------------------------------------------------------------------
// bf16x3 GEMM via mma.sync: C[M,N] = A[M,K] @ Bt[N,K]^T + bias
// ---------------------------------------------------------------------------
#define LDA 40

__global__ __launch_bounds__(256)
void gemm_mma_kernel(const __nv_bfloat16* __restrict__ Ah,
                     const __nv_bfloat16* __restrict__ Al,
                     const __nv_bfloat16* __restrict__ Bh,
                     const __nv_bfloat16* __restrict__ Bl,
                     const float* __restrict__ bias,
                     float* __restrict__ C,
                     int M, int N, int K)
{
    __shared__ __nv_bfloat16 sAh[128 * LDA];
    __shared__ __nv_bfloat16 sAl[128 * LDA];
    __shared__ __nv_bfloat16 sBh[128 * LDA];
    __shared__ __nv_bfloat16 sBl[128 * LDA];

    const int tid  = threadIdx.x;
    const int lane = tid & 31;
    const int wid  = tid >> 5;
    const int wm   = wid >> 2;
    const int wn   = wid & 3;
    const int m0   = blockIdx.y * 128;
    const int n0   = blockIdx.x * 128;

    const uint32_t uAh = smem_u32(sAh);
    const uint32_t uAl = smem_u32(sAl);
    const uint32_t uBh = smem_u32(sBh);
    const uint32_t uBl = smem_u32(sBl);

    float acc[4][4][4];
#pragma unroll
    for (int i = 0; i < 4; ++i)
#pragma unroll
        for (int j = 0; j < 4; ++j)
#pragma unroll
            for (int r = 0; r < 4; ++r) acc[i][j][r] = 0.f;

    const int a_row = lane & 15;
    const int a_kb  = (lane >> 4) * 8;
    const int b_row = lane & 7;
    const int b_kb  = ((lane >> 3) & 1) * 8;

    for (int k0 = 0; k0 < K; k0 += 32) {
        __syncthreads();
#pragma unroll
        for (int it = 0; it < 2; ++it) {
            int chunk = tid + it * 256;
            int r = chunk >> 2;
            int c = chunk & 3;
            long gA = (long)(m0 + r) * K + k0 + c * 8;
            long gB = (long)(n0 + r) * K + k0 + c * 8;
            int so = r * LDA + c * 8;
            *(uint4*)&sAh[so] = *(const uint4*)&Ah[gA];
            *(uint4*)&sAl[so] = *(const uint4*)&Al[gA];
            *(uint4*)&sBh[so] = *(const uint4*)&Bh[gB];
            *(uint4*)&sBl[so] = *(const uint4*)&Bl[gB];
        }
        __syncthreads();

#pragma unroll
        for (int ks = 0; ks < 2; ++ks) {
            const int kc = ks * 16;
            uint32_t bh[4][2], bl[4][2];
#pragma unroll
            for (int j = 0; j < 4; ++j) {
                uint32_t off = ((wn * 32 + j * 8 + b_row) * LDA + kc + b_kb) * 2;
                LDM_X2(bh[j], uBh + off);
                LDM_X2(bl[j], uBl + off);
            }
#pragma unroll
            for (int i = 0; i < 4; ++i) {
                uint32_t off = ((wm * 64 + i * 16 + a_row) * LDA + kc + a_kb) * 2;
                uint32_t ah[4], al[4];
                LDM_X4(ah, uAh + off);
                LDM_X4(al, uAl + off);
#pragma unroll
                for (int j = 0; j < 4; ++j) {
                    MMA_BF16(acc[i][j], ah, bh[j]);
                    MMA_BF16(acc[i][j], ah, bl[j]);
                    MMA_BF16(acc[i][j], al, bh[j]);
                }
            }
        }
    }

    const int qr = lane >> 2;
    const int qc = (lane & 3) * 2;
#pragma unroll
    for (int i = 0; i < 4; ++i) {
#pragma unroll
        for (int j = 0; j < 4; ++j) {
            int col = n0 + wn * 32 + j * 8 + qc;
            float b0 = __ldg(&bias[col]);
            float b1 = __ldg(&bias[col + 1]);
            long r0 = m0 + wm * 64 + i * 16 + qr;
            float2 v0 = make_float2(acc[i][j][0] + b0, acc[i][j][1] + b1);
            float2 v1 = make_float2(acc[i][j][2] + b0, acc[i][j][3] + b1);
            *(float2*)&C[r0 * N + col]       = v0;
            *(float2*)&C[(r0 + 8) * N + col] = v1;
        }
    }
}

// ---------------------------------------------------------------------------
// Flash attention via mma.sync (bf16 hi/lo split, fp32 accum, causal).
// Block = 128 q rows of one (b,h); 8 warps x 16 rows. K/V tiles of 128.
// Output written directly as bf16 hi/lo pairs (feeds proj GEMM).
// ---------------------------------------------------------------------------
#define FA_LDA 72   // 64 cols + 8 pad (144B = 9*16B rows -> conflict-free ldmatrix)
#define FA_LDV 72
#define FA_SMEM ((4 * 128 * FA_LDA + 2 * 128 * FA_LDV) * 2)

__global__ __launch_bounds__(256)
void flash_mma_kernel(const float* __restrict__ qkv,
                      __nv_bfloat16* __restrict__ oh,
                      __nv_bfloat16* __restrict__ ol)
{
    extern __shared__ __nv_bfloat16 fsm[];
    __nv_bfloat16* sQh = fsm;
    __nv_bfloat16* sQl = sQh + 128 * FA_LDA;
    __nv_bfloat16* sKh = sQl + 128 * FA_LDA;
    __nv_bfloat16* sKl = sKh + 128 * FA_LDA;
    __nv_bfloat16* sVh = sKl + 128 * FA_LDA;
    __nv_bfloat16* sVl = sVh + 128 * FA_LDV;

    const int tid  = threadIdx.x;
    const int lane = tid & 31;
    const int wq   = tid >> 5;                       // q-row group
    const int qt   = (int)gridDim.x - 1 - (int)blockIdx.x;  // big tiles first
    const int bh   = blockIdx.y;
    const int b    = bh / H_;
    const int h    = bh - b * H_;
    const int q0   = qt * 128;
    const long rowbase = (long)b * S_ * QKV_N + h * HD;

    // load Q tile (scaled by 1/8), split to hi/lo
#pragma unroll
    for (int it = 0; it < 8; ++it) {
        int f4 = tid + it * 256;          // 2048 float4
        int r  = f4 >> 4;
        int c  = (f4 & 15) * 4;
        float4 v = *(const float4*)&qkv[rowbase + (long)(q0 + r) * QKV_N + c];
        v.x *= 0.125f; v.y *= 0.125f; v.z *= 0.125f; v.w *= 0.125f;
        store_split4(&sQh[r * FA_LDA + c], &sQl[r * FA_LDA + c], v);
    }
    __syncthreads();

    // hoist Q fragments (constant across k tiles)
    uint32_t qfh[4][4], qfl[4][4];
    {
        int arow = wq * 16 + (lane & 15);
        int acol = (lane >> 4) * 8;
#pragma unroll
        for (int ks = 0; ks < 4; ++ks) {
            uint32_t off = (arow * FA_LDA + ks * 16 + acol) * 2;
            LDM_X4(qfh[ks], smem_u32(sQh) + off);
            LDM_X4(qfl[ks], smem_u32(sQl) + off);
        }
    }

    float o[8][4];
#pragma unroll
    for (int j = 0; j < 8; ++j)
#pragma unroll
        for (int r = 0; r < 4; ++r) o[j][r] = 0.f;
    float rm[2] = {-1e30f, -1e30f};
    float rl[2] = {0.f, 0.f};

    const int r0 = lane >> 2;
    const int c0 = (lane & 3) * 2;

    for (int kt = 0; kt <= qt; ++kt) {
        __syncthreads();
        // load K, V tiles (fp32 -> hi/lo bf16)
        const int k0 = kt * 128;
#pragma unroll
        for (int it = 0; it < 8; ++it) {
            int f4 = tid + it * 256;
            int r  = f4 >> 4;
            int c  = (f4 & 15) * 4;
            long base = rowbase + (long)(k0 + r) * QKV_N + c;
            float4 kv = *(const float4*)&qkv[base + D_];
            store_split4(&sKh[r * FA_LDA + c], &sKl[r * FA_LDA + c], kv);
            float4 vv = *(const float4*)&qkv[base + 2 * D_];
            store_split4(&sVh[r * FA_LDV + c], &sVl[r * FA_LDV + c], vv);
        }
        __syncthreads();

        // S = Q K^T  (16 n-tiles of 8 keys)
        float sc[16][4];
#pragma unroll
        for (int j = 0; j < 16; ++j)
#pragma unroll
            for (int r = 0; r < 4; ++r) sc[j][r] = 0.f;

        {
            int krow = (lane & 15);
            int kcol = (lane >> 4) * 8;
#pragma unroll
            for (int j2 = 0; j2 < 8; ++j2) {
#pragma unroll
                for (int ks = 0; ks < 4; ++ks) {
                    uint32_t off = ((j2 * 16 + krow) * FA_LDA + ks * 16 + kcol) * 2;
                    uint32_t kh[4], kl[4];
                    LDM_X4(kh, smem_u32(sKh) + off);
                    LDM_X4(kl, smem_u32(sKl) + off);
                    // kh = {b0(t0), b0(t1), b1(t0), b1(t1)}
                    MMA_BF16R(sc[2*j2],   qfh[ks], kh[0], kh[2]);
                    MMA_BF16R(sc[2*j2],   qfh[ks], kl[0], kl[2]);
                    MMA_BF16R(sc[2*j2],   qfl[ks], kh[0], kh[2]);
                    MMA_BF16R(sc[2*j2+1], qfh[ks], kh[1], kh[3]);
                    MMA_BF16R(sc[2*j2+1], qfh[ks], kl[1], kl[3]);
                    MMA_BF16R(sc[2*j2+1], qfl[ks], kh[1], kh[3]);
                }
            }
        }

        // causal mask on diagonal tile
        if (kt == qt) {
            int row0 = wq * 16 + r0;
            int row1 = row0 + 8;
#pragma unroll
            for (int j = 0; j < 16; ++j) {
                int col = j * 8 + c0;
                if (col     > row0) sc[j][0] = -1e30f;
                if (col + 1 > row0) sc[j][1] = -1e30f;
                if (col     > row1) sc[j][2] = -1e30f;
                if (col + 1 > row1) sc[j][3] = -1e30f;
            }
        }

        // online softmax (rows r0 and r0+8)
        float mx0 = -1e30f, mx1 = -1e30f;
#pragma unroll
        for (int j = 0; j < 16; ++j) {
            mx0 = fmaxf(mx0, fmaxf(sc[j][0], sc[j][1]));
            mx1 = fmaxf(mx1, fmaxf(sc[j][2], sc[j][3]));
        }
        mx0 = fmaxf(mx0, __shfl_xor_sync(0xffffffffu, mx0, 1));
        mx0 = fmaxf(mx0, __shfl_xor_sync(0xffffffffu, mx0, 2));
        mx1 = fmaxf(mx1, __shfl_xor_sync(0xffffffffu, mx1, 1));
        mx1 = fmaxf(mx1, __shfl_xor_sync(0xffffffffu, mx1, 2));

        float mn0 = fmaxf(rm[0], mx0);
        float mn1 = fmaxf(rm[1], mx1);
        float a0 = __expf(rm[0] - mn0);
        float a1 = __expf(rm[1] - mn1);
        rm[0] = mn0; rm[1] = mn1;

        float s0 = 0.f, s1 = 0.f;
#pragma unroll
        for (int j = 0; j < 16; ++j) {
            sc[j][0] = __expf(sc[j][0] - mn0); s0 += sc[j][0];
            sc[j][1] = __expf(sc[j][1] - mn0); s0 += sc[j][1];
            sc[j][2] = __expf(sc[j][2] - mn1); s1 += sc[j][2];
            sc[j][3] = __expf(sc[j][3] - mn1); s1 += sc[j][3];
        }
        s0 += __shfl_xor_sync(0xffffffffu, s0, 1);
        s0 += __shfl_xor_sync(0xffffffffu, s0, 2);
        s1 += __shfl_xor_sync(0xffffffffu, s1, 1);
        s1 += __shfl_xor_sync(0xffffffffu, s1, 2);
        rl[0] = rl[0] * a0 + s0;
        rl[1] = rl[1] * a1 + s1;
#pragma unroll
        for (int j = 0; j < 8; ++j) {
            o[j][0] *= a0; o[j][1] *= a0;
            o[j][2] *= a1; o[j][3] *= a1;
        }

        // O += P V   (P packed in place from sc fragments)
        {
            int vr = (lane & 7) + ((lane >> 3) & 1) * 8;
            int vc = (lane >> 4) * 8;
#pragma unroll
            for (int ks2 = 0; ks2 < 8; ++ks2) {
                uint32_t ph[4], pl[4];
#pragma unroll
                for (int half = 0; half < 2; ++half) {
                    const float* p = sc[2*ks2 + half];
                    float h0f = __bfloat162float(__float2bfloat16(p[0]));
                    float h1f = __bfloat162float(__float2bfloat16(p[1]));
                    float h2f = __bfloat162float(__float2bfloat16(p[2]));
                    float h3f = __bfloat162float(__float2bfloat16(p[3]));
                    ph[2*half]   = pack_bf2(h0f, h1f);
                    ph[2*half+1] = pack_bf2(h2f, h3f);
                    pl[2*half]   = pack_bf2(p[0]-h0f, p[1]-h1f);
                    pl[2*half+1] = pack_bf2(p[2]-h2f, p[3]-h3f);
                }
                // A-frag order: a0=(r,k0-7) a1=(r+8,k0-7) a2=(r,k8-15) a3=(r+8,k8-15)
                uint32_t pfh[4] = {ph[0], ph[1], ph[2], ph[3]};
                uint32_t pfl[4] = {pl[0], pl[1], pl[2], pl[3]};
#pragma unroll
                for (int jp = 0; jp < 4; ++jp) {
                    uint32_t voff = ((ks2 * 16 + vr) * FA_LDV + jp * 16 + vc) * 2;
                    uint32_t vh[4], vl[4];
                    LDM_X4T(vh, smem_u32(sVh) + voff);
                    LDM_X4T(vl, smem_u32(sVl) + voff);
                    // vh = {b0(t0), b1(t0), b0(t1), b1(t1)}
                    MMA_BF16R(o[2*jp],   pfh, vh[0], vh[1]);
                    MMA_BF16R(o[2*jp],   pfh, vl[0], vl[1]);
                    MMA_BF16R(o[2*jp],   pfl, vh[0], vh[1]);
                    MMA_BF16R(o[2*jp+1], pfh, vh[2], vh[3]);
                    MMA_BF16R(o[2*jp+1], pfh, vl[2], vl[3]);
                    MMA_BF16R(o[2*jp+1], pfl, vh[2], vh[3]);
                }
            }
        }
    }

    // epilogue: normalize, split to bf16 hi/lo, store
    float inv0 = 1.f / rl[0];
    float inv1 = 1.f / rl[1];
    long grow0 = (long)b * S_ + q0 + wq * 16 + r0;
#pragma unroll
    for (int j = 0; j < 8; ++j) {
        int col = h * HD + j * 8 + c0;
        {
            float v0 = o[j][0] * inv0, v1 = o[j][1] * inv0;
            __nv_bfloat16 h0 = __float2bfloat16(v0), h1 = __float2bfloat16(v1);
            long off = grow0 * D_ + col;
            *(__nv_bfloat162*)&oh[off] = __nv_bfloat162(h0, h1);
            *(__nv_bfloat162*)&ol[off] = __nv_bfloat162(
                __float2bfloat16(v0 - __bfloat162float(h0)),
                __float2bfloat16(v1 - __bfloat162float(h1)));
        }
        {
            float v0 = o[j][2] * inv1, v1 = o[j][3] * inv1;
            __nv_bfloat16 h0 = __float2bfloat16(v0), h1 = __float2bfloat16(v1);
            long off = (grow0 + 8) * D_ + col;
            *(__nv_bfloat162*)&oh[off] = __nv_bfloat162(h0, h1);
            *(__nv_bfloat162*)&ol[off] = __nv_bfloat162(
                __float2bfloat16(v0 - __bfloat162float(h0)),
                __float2bfloat16(v1 - __bfloat162float(h1)));
        }
    }
}

// ---------------------------------------------------------------------------
extern "C" void kernel_launch(void* const* d_in, const int* in_sizes, int n_in,
                              void* d_out, int out_size)
{
    const float* x    = (const float*)d_in[0];
    const float* Wqkv = (const float*)d_in[1];
    const float* bqkv = (const float*)d_in[2];
    const float* Wp   = (const float*)d_in[3];
    const float* bp   = (const float*)d_in[4];
    float* out = (float*)d_out;

    float *qkv;
    __nv_bfloat16 *ah, *al, *bh, *bl;
    cudaGetSymbolAddress((void**)&qkv, g_qkv);
    cudaGetSymbolAddress((void**)&ah, g_ah);
    cudaGetSymbolAddress((void**)&al, g_al);
    cudaGetSymbolAddress((void**)&bh, g_bh);
    cudaGetSymbolAddress((void**)&bl, g_bl);

    const int n4 = M_ * D_ / 4;

    // 1) split x, transpose+split Wqkv, tensor-core QKV GEMM
    split_kernel<<<(n4 + 255) / 256, 256>>>(x, ah, al, n4);
    transpose_split_kernel<<<dim3(QKV_N / 32, D_ / 32), dim3(32, 8)>>>(Wqkv, bh, bl, D_, QKV_N);
    gemm_mma_kernel<<<dim3(QKV_N / 128, M_ / 128), 256>>>(
        ah, al, bh, bl, bqkv, qkv, M_, QKV_N, D_);

    // 2) causal flash attention on tensor cores; writes hi/lo bf16 directly
    cudaFuncSetAttribute(flash_mma_kernel,
                         cudaFuncAttributeMaxDynamicSharedMemorySize, FA_SMEM);
    flash_mma_kernel<<<dim3(S_ / 128, B_ * H_), 256, FA_SMEM>>>(qkv, ah, al);

    // 3) transpose+split Wp, tensor-core proj GEMM
    transpose_split_kernel<<<dim3(D_ / 32, D_ / 32), dim3(32, 8)>>>(Wp, bh, bl, D_, D_);
    gemm_mma_kernel<<<dim3(D_ / 128, M_ / 128), 256>>>(
        ah, al, bh, bl, bp, out, M_, D_, D_);
}

// round 8
// speedup vs baseline: 2.7198x; 1.2452x over previous
#include <cuda_runtime.h>
#include <cuda_bf16.h>
#include <cstdint>
#include <math.h>

#define B_    4
#define S_    2048
#define D_    768
#define H_    12
#define HD    64
#define QKV_N (3*D_)      // 2304
#define M_    (B_*S_)     // 8192

// Scratch (no cudaMalloc allowed)
__device__ __nv_bfloat16 g_qh[M_ * QKV_N];   // qkv hi (Q pre-scaled)
__device__ __nv_bfloat16 g_ql[M_ * QKV_N];   // qkv lo
__device__ __nv_bfloat16 g_ah[M_ * D_];
__device__ __nv_bfloat16 g_al[M_ * D_];
__device__ __nv_bfloat16 g_bh[QKV_N * D_];
__device__ __nv_bfloat16 g_bl[QKV_N * D_];

// ---------------------------------------------------------------------------
__device__ __forceinline__ uint32_t smem_u32(const void* p) {
    uint32_t a;
    asm("{ .reg .u64 t; cvta.to.shared.u64 t, %1; cvt.u32.u64 %0, t; }" : "=r"(a) : "l"(p));
    return a;
}

#define CP_ASYNC16(dst, src) \
    asm volatile("cp.async.cg.shared.global [%0], [%1], 16;" :: "r"(dst), "l"(src))
#define CP_COMMIT() asm volatile("cp.async.commit_group;" ::: "memory")
#define CP_WAIT0()  asm volatile("cp.async.wait_group 0;" ::: "memory")

#define LDM_X4(r, addr) \
    asm volatile("ldmatrix.sync.aligned.m8n8.x4.shared.b16 {%0,%1,%2,%3}, [%4];" \
        : "=r"((r)[0]), "=r"((r)[1]), "=r"((r)[2]), "=r"((r)[3]) : "r"(addr))
#define LDM_X4T(r, addr) \
    asm volatile("ldmatrix.sync.aligned.m8n8.x4.trans.shared.b16 {%0,%1,%2,%3}, [%4];" \
        : "=r"((r)[0]), "=r"((r)[1]), "=r"((r)[2]), "=r"((r)[3]) : "r"(addr))
#define LDM_X2(r, addr) \
    asm volatile("ldmatrix.sync.aligned.m8n8.x2.shared.b16 {%0,%1}, [%2];" \
        : "=r"((r)[0]), "=r"((r)[1]) : "r"(addr))
#define MMA_BF16(d, a, b) \
    asm volatile("mma.sync.aligned.m16n8k16.row.col.f32.bf16.bf16.f32 " \
        "{%0,%1,%2,%3}, {%4,%5,%6,%7}, {%8,%9}, {%0,%1,%2,%3};" \
        : "+f"((d)[0]), "+f"((d)[1]), "+f"((d)[2]), "+f"((d)[3]) \
        : "r"((a)[0]), "r"((a)[1]), "r"((a)[2]), "r"((a)[3]), \
          "r"((b)[0]), "r"((b)[1]))
#define MMA_BF16R(d, a, b0r, b1r) \
    asm volatile("mma.sync.aligned.m16n8k16.row.col.f32.bf16.bf16.f32 " \
        "{%0,%1,%2,%3}, {%4,%5,%6,%7}, {%8,%9}, {%0,%1,%2,%3};" \
        : "+f"((d)[0]), "+f"((d)[1]), "+f"((d)[2]), "+f"((d)[3]) \
        : "r"((a)[0]), "r"((a)[1]), "r"((a)[2]), "r"((a)[3]), \
          "r"(b0r), "r"(b1r))

__device__ __forceinline__ uint32_t pack_bf2(float lo, float hi) {
    uint32_t r;
    asm("cvt.rn.bf16x2.f32 %0, %1, %2;" : "=r"(r) : "f"(hi), "f"(lo));
    return r;
}

__device__ __forceinline__ void store_split4(__nv_bfloat16* ph, __nv_bfloat16* pl, float4 v) {
    __nv_bfloat16 h0 = __float2bfloat16(v.x), h1 = __float2bfloat16(v.y);
    __nv_bfloat16 h2 = __float2bfloat16(v.z), h3 = __float2bfloat16(v.w);
    *(__nv_bfloat162*)(ph)     = __nv_bfloat162(h0, h1);
    *(__nv_bfloat162*)(ph + 2) = __nv_bfloat162(h2, h3);
    *(__nv_bfloat162*)(pl)     = __nv_bfloat162(
        __float2bfloat16(v.x - __bfloat162float(h0)),
        __float2bfloat16(v.y - __bfloat162float(h1)));
    *(__nv_bfloat162*)(pl + 2) = __nv_bfloat162(
        __float2bfloat16(v.z - __bfloat162float(h2)),
        __float2bfloat16(v.w - __bfloat162float(h3)));
}

// ---------------------------------------------------------------------------
__global__ void split_kernel(const float* __restrict__ in,
                             __nv_bfloat16* __restrict__ hi,
                             __nv_bfloat16* __restrict__ lo, int n4)
{
    int i = blockIdx.x * blockDim.x + threadIdx.x;
    if (i >= n4) return;
    float4 v = ((const float4*)in)[i];
    store_split4(hi + 4 * (long)i, lo + 4 * (long)i, v);
}

__global__ void transpose_split_kernel(const float* __restrict__ W,
                                       __nv_bfloat16* __restrict__ Bh,
                                       __nv_bfloat16* __restrict__ Bl,
                                       int K, int N)
{
    __shared__ float t[32][33];
    int n0 = blockIdx.x * 32, k0 = blockIdx.y * 32;
    int tx = threadIdx.x, ty = threadIdx.y;
#pragma unroll
    for (int j = 0; j < 4; ++j)
        t[ty + j*8][tx] = W[(long)(k0 + ty + j*8) * N + n0 + tx];
    __syncthreads();
#pragma unroll
    for (int j = 0; j < 4; ++j) {
        float v = t[tx][ty + j*8];
        __nv_bfloat16 h = __float2bfloat16(v);
        __nv_bfloat16 l = __float2bfloat16(v - __bfloat162float(h));
        long o = (long)(n0 + ty + j*8) * K + k0 + tx;
        Bh[o] = h;
        Bl[o] = l;
    }
}

// ---------------------------------------------------------------------------
// bf16x3 GEMM via mma.sync, cp.async double-buffered.
// SPLIT_OUT=1: write C as bf16 hi/lo (cols < scale_cols multiplied by scale).
// ---------------------------------------------------------------------------
#define LDA 40
#define G_ARR (128 * LDA * 2)        // 10240 B per array
#define G_STAGE (4 * G_ARR)          // 40960
#define G_SMEM (2 * G_STAGE)         // 81920

template<int SPLIT_OUT>
__global__ __launch_bounds__(256)
void gemm_mma_kernel(const __nv_bfloat16* __restrict__ Ah,
                     const __nv_bfloat16* __restrict__ Al,
                     const __nv_bfloat16* __restrict__ Bh,
                     const __nv_bfloat16* __restrict__ Bl,
                     const float* __restrict__ bias,
                     float* __restrict__ C,
                     __nv_bfloat16* __restrict__ Ch,
                     __nv_bfloat16* __restrict__ Cl,
                     int M, int N, int K, int scale_cols, float scale)
{
    extern __shared__ __nv_bfloat16 gsm[];
    const uint32_t sb = smem_u32(gsm);

    const int tid  = threadIdx.x;
    const int lane = tid & 31;
    const int wid  = tid >> 5;
    const int wm   = wid >> 2;
    const int wn   = wid & 3;
    const int m0   = blockIdx.y * 128;
    const int n0   = blockIdx.x * 128;
    const int KT   = K / 32;

    const __nv_bfloat16* srcs[4] = {Ah, Al, Bh, Bl};
    const int row0s[4] = {m0, m0, n0, n0};

    float acc[4][4][4];
#pragma unroll
    for (int i = 0; i < 4; ++i)
#pragma unroll
        for (int j = 0; j < 4; ++j)
#pragma unroll
            for (int r = 0; r < 4; ++r) acc[i][j][r] = 0.f;

    const int a_row = lane & 15;
    const int a_kb  = (lane >> 4) * 8;
    const int b_row = lane & 7;
    const int b_kb  = ((lane >> 3) & 1) * 8;

    auto cp_issue = [&](int kt, int stage) {
        const int k0 = kt * 32;
        const uint32_t sdst = sb + stage * G_STAGE;
#pragma unroll
        for (int t = 0; t < 4; ++t) {
            const __nv_bfloat16* src = srcs[t];
            const int r0 = row0s[t];
#pragma unroll
            for (int it = 0; it < 2; ++it) {
                int chunk = tid + it * 256;
                int r = chunk >> 2, c = chunk & 3;
                uint32_t dst = sdst + t * G_ARR + (r * LDA + c * 8) * 2;
                CP_ASYNC16(dst, (const void*)&src[(long)(r0 + r) * K + k0 + c * 8]);
            }
        }
    };

    cp_issue(0, 0);
    CP_COMMIT();

    for (int kt = 0; kt < KT; ++kt) {
        CP_WAIT0();
        __syncthreads();
        if (kt + 1 < KT) { cp_issue(kt + 1, (kt + 1) & 1); CP_COMMIT(); }

        const uint32_t ub  = sb + (kt & 1) * G_STAGE;
        const uint32_t uAh = ub, uAl = ub + G_ARR, uBh = ub + 2 * G_ARR, uBl = ub + 3 * G_ARR;

#pragma unroll
        for (int ks = 0; ks < 2; ++ks) {
            const int kc = ks * 16;
            uint32_t bh[4][2], bl[4][2];
#pragma unroll
            for (int j = 0; j < 4; ++j) {
                uint32_t off = ((wn * 32 + j * 8 + b_row) * LDA + kc + b_kb) * 2;
                LDM_X2(bh[j], uBh + off);
                LDM_X2(bl[j], uBl + off);
            }
#pragma unroll
            for (int i = 0; i < 4; ++i) {
                uint32_t off = ((wm * 64 + i * 16 + a_row) * LDA + kc + a_kb) * 2;
                uint32_t ah[4], al[4];
                LDM_X4(ah, uAh + off);
                LDM_X4(al, uAl + off);
#pragma unroll
                for (int j = 0; j < 4; ++j) {
                    MMA_BF16(acc[i][j], ah, bh[j]);
                    MMA_BF16(acc[i][j], ah, bl[j]);
                    MMA_BF16(acc[i][j], al, bh[j]);
                }
            }
        }
        __syncthreads();
    }

    const int qr = lane >> 2;
    const int qc = (lane & 3) * 2;
#pragma unroll
    for (int i = 0; i < 4; ++i) {
#pragma unroll
        for (int j = 0; j < 4; ++j) {
            int col = n0 + wn * 32 + j * 8 + qc;
            float b0 = __ldg(&bias[col]);
            float b1 = __ldg(&bias[col + 1]);
            long r0 = m0 + wm * 64 + i * 16 + qr;
            float v00 = acc[i][j][0] + b0, v01 = acc[i][j][1] + b1;
            float v10 = acc[i][j][2] + b0, v11 = acc[i][j][3] + b1;
            if (SPLIT_OUT) {
                float s = (col < scale_cols) ? scale : 1.f;
                v00 *= s; v01 *= s; v10 *= s; v11 *= s;
                __nv_bfloat16 h00 = __float2bfloat16(v00), h01 = __float2bfloat16(v01);
                __nv_bfloat16 h10 = __float2bfloat16(v10), h11 = __float2bfloat16(v11);
                *(__nv_bfloat162*)&Ch[r0 * N + col] = __nv_bfloat162(h00, h01);
                *(__nv_bfloat162*)&Cl[r0 * N + col] = __nv_bfloat162(
                    __float2bfloat16(v00 - __bfloat162float(h00)),
                    __float2bfloat16(v01 - __bfloat162float(h01)));
                *(__nv_bfloat162*)&Ch[(r0 + 8) * N + col] = __nv_bfloat162(h10, h11);
                *(__nv_bfloat162*)&Cl[(r0 + 8) * N + col] = __nv_bfloat162(
                    __float2bfloat16(v10 - __bfloat162float(h10)),
                    __float2bfloat16(v11 - __bfloat162float(h11)));
            } else {
                *(float2*)&C[r0 * N + col]       = make_float2(v00, v01);
                *(float2*)&C[(r0 + 8) * N + col] = make_float2(v10, v11);
            }
        }
    }
}

// ---------------------------------------------------------------------------
// Flash attention, bf16 hi/lo inputs (pre-split, Q pre-scaled), cp.async
// double-buffered K/V. Block = 128 q rows of one (b,h). Causal.
// ---------------------------------------------------------------------------
#define FA_LD 72
#define FA_ARR (128 * FA_LD * 2)          // 18432
#define FA_KV0 (2 * FA_ARR)               // Q hi+lo region
#define FA_STAGE (4 * FA_ARR)             // 73728
#define FA_SMEM (FA_KV0 + 2 * FA_STAGE)   // 184320

__global__ __launch_bounds__(256)
void flash_mma_kernel(const __nv_bfloat16* __restrict__ qh,
                      const __nv_bfloat16* __restrict__ ql,
                      __nv_bfloat16* __restrict__ oh,
                      __nv_bfloat16* __restrict__ ol)
{
    extern __shared__ __nv_bfloat16 fsm[];
    const uint32_t sb = smem_u32(fsm);

    const int tid  = threadIdx.x;
    const int lane = tid & 31;
    const int wq   = tid >> 5;
    const int qt   = (int)gridDim.x - 1 - (int)blockIdx.x;  // big tiles first
    const int bh   = blockIdx.y;
    const int b    = bh / H_;
    const int h    = bh - b * H_;
    const int q0   = qt * 128;
    const long rowbase = (long)b * S_ * QKV_N + h * HD;

    const __nv_bfloat16* kvsrc[4] = {qh + D_, ql + D_, qh + 2 * D_, ql + 2 * D_};

    // prologue: Q (hi/lo) + KV stage 0 via cp.async
    {
        const __nv_bfloat16* qsrc[2] = {qh, ql};
#pragma unroll
        for (int t = 0; t < 2; ++t) {
#pragma unroll
            for (int it = 0; it < 4; ++it) {
                int chunk = tid + it * 256;
                int r = chunk >> 3, c = chunk & 7;
                uint32_t dst = sb + t * FA_ARR + (r * FA_LD + c * 8) * 2;
                CP_ASYNC16(dst, (const void*)&qsrc[t][rowbase + (long)(q0 + r) * QKV_N + c * 8]);
            }
        }
    }
    auto kv_issue = [&](int kt, int stage) {
        const int k0 = kt * 128;
        const uint32_t sdst = sb + FA_KV0 + stage * FA_STAGE;
#pragma unroll
        for (int t = 0; t < 4; ++t) {
#pragma unroll
            for (int it = 0; it < 4; ++it) {
                int chunk = tid + it * 256;
                int r = chunk >> 3, c = chunk & 7;
                uint32_t dst = sdst + t * FA_ARR + (r * FA_LD + c * 8) * 2;
                CP_ASYNC16(dst, (const void*)&kvsrc[t][rowbase + (long)(k0 + r) * QKV_N + c * 8]);
            }
        }
    };
    kv_issue(0, 0);
    CP_COMMIT();
    CP_WAIT0();
    __syncthreads();

    // hoist Q fragments
    uint32_t qfh[4][4], qfl[4][4];
    {
        int arow = wq * 16 + (lane & 15);
        int acol = (lane >> 4) * 8;
#pragma unroll
        for (int ks = 0; ks < 4; ++ks) {
            uint32_t off = (arow * FA_LD + ks * 16 + acol) * 2;
            LDM_X4(qfh[ks], sb + off);
            LDM_X4(qfl[ks], sb + FA_ARR + off);
        }
    }

    float o[8][4];
#pragma unroll
    for (int j = 0; j < 8; ++j)
#pragma unroll
        for (int r = 0; r < 4; ++r) o[j][r] = 0.f;
    float rm[2] = {-1e30f, -1e30f};
    float rl[2] = {0.f, 0.f};

    const int r0 = lane >> 2;
    const int c0 = (lane & 3) * 2;

    for (int kt = 0; kt <= qt; ++kt) {
        if (kt < qt) { kv_issue(kt + 1, (kt + 1) & 1); CP_COMMIT(); }

        const uint32_t ukv = sb + FA_KV0 + (kt & 1) * FA_STAGE;
        const uint32_t uKh = ukv, uKl = ukv + FA_ARR;
        const uint32_t uVh = ukv + 2 * FA_ARR, uVl = ukv + 3 * FA_ARR;

        // S = Q K^T
        float sc[16][4];
#pragma unroll
        for (int j = 0; j < 16; ++j)
#pragma unroll
            for (int r = 0; r < 4; ++r) sc[j][r] = 0.f;

        {
            int krow = (lane & 15);
            int kcol = (lane >> 4) * 8;
#pragma unroll
            for (int j2 = 0; j2 < 8; ++j2) {
#pragma unroll
                for (int ks = 0; ks < 4; ++ks) {
                    uint32_t off = ((j2 * 16 + krow) * FA_LD + ks * 16 + kcol) * 2;
                    uint32_t kh[4], kl[4];
                    LDM_X4(kh, uKh + off);
                    LDM_X4(kl, uKl + off);
                    MMA_BF16R(sc[2*j2],   qfh[ks], kh[0], kh[2]);
                    MMA_BF16R(sc[2*j2],   qfh[ks], kl[0], kl[2]);
                    MMA_BF16R(sc[2*j2],   qfl[ks], kh[0], kh[2]);
                    MMA_BF16R(sc[2*j2+1], qfh[ks], kh[1], kh[3]);
                    MMA_BF16R(sc[2*j2+1], qfh[ks], kl[1], kl[3]);
                    MMA_BF16R(sc[2*j2+1], qfl[ks], kh[1], kh[3]);
                }
            }
        }

        if (kt == qt) {
            int row0 = wq * 16 + r0;
            int row1 = row0 + 8;
#pragma unroll
            for (int j = 0; j < 16; ++j) {
                int col = j * 8 + c0;
                if (col     > row0) sc[j][0] = -1e30f;
                if (col + 1 > row0) sc[j][1] = -1e30f;
                if (col     > row1) sc[j][2] = -1e30f;
                if (col + 1 > row1) sc[j][3] = -1e30f;
            }
        }

        // online softmax
        float mx0 = -1e30f, mx1 = -1e30f;
#pragma unroll
        for (int j = 0; j < 16; ++j) {
            mx0 = fmaxf(mx0, fmaxf(sc[j][0], sc[j][1]));
            mx1 = fmaxf(mx1, fmaxf(sc[j][2], sc[j][3]));
        }
        mx0 = fmaxf(mx0, __shfl_xor_sync(0xffffffffu, mx0, 1));
        mx0 = fmaxf(mx0, __shfl_xor_sync(0xffffffffu, mx0, 2));
        mx1 = fmaxf(mx1, __shfl_xor_sync(0xffffffffu, mx1, 1));
        mx1 = fmaxf(mx1, __shfl_xor_sync(0xffffffffu, mx1, 2));

        float mn0 = fmaxf(rm[0], mx0);
        float mn1 = fmaxf(rm[1], mx1);
        float a0 = __expf(rm[0] - mn0);
        float a1 = __expf(rm[1] - mn1);
        rm[0] = mn0; rm[1] = mn1;

        float s0 = 0.f, s1 = 0.f;
#pragma unroll
        for (int j = 0; j < 16; ++j) {
            sc[j][0] = __expf(sc[j][0] - mn0); s0 += sc[j][0];
            sc[j][1] = __expf(sc[j][1] - mn0); s0 += sc[j][1];
            sc[j][2] = __expf(sc[j][2] - mn1); s1 += sc[j][2];
            sc[j][3] = __expf(sc[j][3] - mn1); s1 += sc[j][3];
        }
        s0 += __shfl_xor_sync(0xffffffffu, s0, 1);
        s0 += __shfl_xor_sync(0xffffffffu, s0, 2);
        s1 += __shfl_xor_sync(0xffffffffu, s1, 1);
        s1 += __shfl_xor_sync(0xffffffffu, s1, 2);
        rl[0] = rl[0] * a0 + s0;
        rl[1] = rl[1] * a1 + s1;
#pragma unroll
        for (int j = 0; j < 8; ++j) {
            o[j][0] *= a0; o[j][1] *= a0;
            o[j][2] *= a1; o[j][3] *= a1;
        }

        // O += P V
        {
            int vr = (lane & 7) + ((lane >> 3) & 1) * 8;
            int vc = (lane >> 4) * 8;
#pragma unroll
            for (int ks2 = 0; ks2 < 8; ++ks2) {
                uint32_t ph[4], pl[4];
#pragma unroll
                for (int half = 0; half < 2; ++half) {
                    const float* p = sc[2*ks2 + half];
                    float h0f = __bfloat162float(__float2bfloat16(p[0]));
                    float h1f = __bfloat162float(__float2bfloat16(p[1]));
                    float h2f = __bfloat162float(__float2bfloat16(p[2]));
                    float h3f = __bfloat162float(__float2bfloat16(p[3]));
                    ph[2*half]   = pack_bf2(h0f, h1f);
                    ph[2*half+1] = pack_bf2(h2f, h3f);
                    pl[2*half]   = pack_bf2(p[0]-h0f, p[1]-h1f);
                    pl[2*half+1] = pack_bf2(p[2]-h2f, p[3]-h3f);
                }
                uint32_t pfh[4] = {ph[0], ph[1], ph[2], ph[3]};
                uint32_t pfl[4] = {pl[0], pl[1], pl[2], pl[3]};
#pragma unroll
                for (int jp = 0; jp < 4; ++jp) {
                    uint32_t voff = ((ks2 * 16 + vr) * FA_LD + jp * 16 + vc) * 2;
                    uint32_t vh[4], vl[4];
                    LDM_X4T(vh, uVh + voff);
                    LDM_X4T(vl, uVl + voff);
                    MMA_BF16R(o[2*jp],   pfh, vh[0], vh[1]);
                    MMA_BF16R(o[2*jp],   pfh, vl[0], vl[1]);
                    MMA_BF16R(o[2*jp],   pfl, vh[0], vh[1]);
                    MMA_BF16R(o[2*jp+1], pfh, vh[2], vh[3]);
                    MMA_BF16R(o[2*jp+1], pfh, vl[2], vl[3]);
                    MMA_BF16R(o[2*jp+1], pfl, vh[2], vh[3]);
                }
            }
        }

        if (kt < qt) { CP_WAIT0(); __syncthreads(); }
    }

    // epilogue
    float inv0 = 1.f / rl[0];
    float inv1 = 1.f / rl[1];
    long grow0 = (long)b * S_ + q0 + wq * 16 + r0;
#pragma unroll
    for (int j = 0; j < 8; ++j) {
        int col = h * HD + j * 8 + c0;
        {
            float v0 = o[j][0] * inv0, v1 = o[j][1] * inv0;
            __nv_bfloat16 h0 = __float2bfloat16(v0), h1 = __float2bfloat16(v1);
            long off = grow0 * D_ + col;
            *(__nv_bfloat162*)&oh[off] = __nv_bfloat162(h0, h1);
            *(__nv_bfloat162*)&ol[off] = __nv_bfloat162(
                __float2bfloat16(v0 - __bfloat162float(h0)),
                __float2bfloat16(v1 - __bfloat162float(h1)));
        }
        {
            float v0 = o[j][2] * inv1, v1 = o[j][3] * inv1;
            __nv_bfloat16 h0 = __float2bfloat16(v0), h1 = __float2bfloat16(v1);
            long off = (grow0 + 8) * D_ + col;
            *(__nv_bfloat162*)&oh[off] = __nv_bfloat162(h0, h1);
            *(__nv_bfloat162*)&ol[off] = __nv_bfloat162(
                __float2bfloat16(v0 - __bfloat162float(h0)),
                __float2bfloat16(v1 - __bfloat162float(h1)));
        }
    }
}

// ---------------------------------------------------------------------------
extern "C" void kernel_launch(void* const* d_in, const int* in_sizes, int n_in,
                              void* d_out, int out_size)
{
    const float* x    = (const float*)d_in[0];
    const float* Wqkv = (const float*)d_in[1];
    const float* bqkv = (const float*)d_in[2];
    const float* Wp   = (const float*)d_in[3];
    const float* bp   = (const float*)d_in[4];
    float* out = (float*)d_out;

    __nv_bfloat16 *qh, *ql, *ah, *al, *bh, *bl;
    cudaGetSymbolAddress((void**)&qh, g_qh);
    cudaGetSymbolAddress((void**)&ql, g_ql);
    cudaGetSymbolAddress((void**)&ah, g_ah);
    cudaGetSymbolAddress((void**)&al, g_al);
    cudaGetSymbolAddress((void**)&bh, g_bh);
    cudaGetSymbolAddress((void**)&bl, g_bl);

    cudaFuncSetAttribute(gemm_mma_kernel<1>,
                         cudaFuncAttributeMaxDynamicSharedMemorySize, G_SMEM);
    cudaFuncSetAttribute(gemm_mma_kernel<0>,
                         cudaFuncAttributeMaxDynamicSharedMemorySize, G_SMEM);
    cudaFuncSetAttribute(flash_mma_kernel,
                         cudaFuncAttributeMaxDynamicSharedMemorySize, FA_SMEM);

    const int n4 = M_ * D_ / 4;

    // 1) split x; transpose+split Wqkv; QKV GEMM -> bf16 hi/lo (Q scaled 0.125)
    split_kernel<<<(n4 + 255) / 256, 256>>>(x, ah, al, n4);
    transpose_split_kernel<<<dim3(QKV_N / 32, D_ / 32), dim3(32, 8)>>>(Wqkv, bh, bl, D_, QKV_N);
    gemm_mma_kernel<1><<<dim3(QKV_N / 128, M_ / 128), 256, G_SMEM>>>(
        ah, al, bh, bl, bqkv, nullptr, qh, ql, M_, QKV_N, D_, D_, 0.125f);

    // 2) flash attention (bf16 hi/lo in, bf16 hi/lo out)
    flash_mma_kernel<<<dim3(S_ / 128, B_ * H_), 256, FA_SMEM>>>(qh, ql, ah, al);

    // 3) transpose+split Wp; proj GEMM -> fp32 out
    transpose_split_kernel<<<dim3(D_ / 32, D_ / 32), dim3(32, 8)>>>(Wp, bh, bl, D_, D_);
    gemm_mma_kernel<0><<<dim3(D_ / 128, M_ / 128), 256, G_SMEM>>>(
        ah, al, bh, bl, bp, out, nullptr, nullptr, M_, D_, D_, 0, 1.f);
}